// round 2
// baseline (speedup 1.0000x reference)
#include <cuda_runtime.h>
#include <cstdint>

// MazeBrain: recurrent adaptive-LIF, T=1200, B=16, N=1024.
// 8-CTA cluster per batch; spike bitmaps pushed via DSMEM; mbarrier cluster
// barrier per step; sparse gather of W rows.

#define T_STEPS 1200
#define BATCH   16
#define NN      1024
#define WHIST   1000
#define CSIZE   8
#define TPB     128
#define NPC     (NN / CSIZE)   // 128 neurons per CTA

__device__ __forceinline__ uint32_t smem_u32(const void* p) {
    return (uint32_t)__cvta_generic_to_shared(p);
}
__device__ __forceinline__ uint32_t mapa_u32(uint32_t addr, uint32_t rank) {
    uint32_t r;
    asm("mapa.shared::cluster.u32 %0, %1, %2;" : "=r"(r) : "r"(addr), "r"(rank));
    return r;
}

__global__ void __cluster_dims__(CSIZE, 1, 1) __launch_bounds__(TPB, 1)
mazebrain_kernel(const float* __restrict__ Iext,   // [T,B,N]
                 const float* __restrict__ W,      // [N,N]
                 float* __restrict__ out)          // [2,T,B,N]
{
    const int cta  = blockIdx.x;
    const int b    = cta >> 3;
    const int rank = cta & 7;
    const int tid  = threadIdx.x;
    const int m    = rank * NPC + tid;   // this thread's post-neuron (0..1023)
    const int lane = tid & 31;
    const int wid  = tid >> 5;

    __shared__ uint64_t mbar;
    __shared__ uint32_t bitmap[2][32];   // full-batch spike bitmap (1024 bits), double-buffered
    __shared__ int      combined[NN];    // dense spike list
    __shared__ int      s_tot;

    if (tid == 0) {
        asm volatile("mbarrier.init.shared.b64 [%0], %1;"
                     :: "r"(smem_u32(&mbar)), "r"((uint32_t)CSIZE) : "memory");
    }
    if (tid < 32) bitmap[0][tid] = 0;    // bitmap[1] is fully overwritten in step 0
    __syncthreads();
    // all CTAs' mbarriers + initial bitmap visible cluster-wide before any remote op
    asm volatile("barrier.cluster.arrive.aligned;" ::: "memory");
    asm volatile("barrier.cluster.wait.aligned;"   ::: "memory");

    // precompute remote addresses: my warp's bitmap word on every peer, peers' mbars
    uint32_t rword[2][CSIZE];
    uint32_t rmbar[CSIZE];
    {
        uint32_t la0 = smem_u32(&bitmap[0][rank * 4 + wid]);
        uint32_t la1 = smem_u32(&bitmap[1][rank * 4 + wid]);
        uint32_t lm  = smem_u32(&mbar);
#pragma unroll
        for (int r = 0; r < CSIZE; r++) {
            rword[0][r] = mapa_u32(la0, r);
            rword[1][r] = mapa_u32(la1, r);
            rmbar[r]    = mapa_u32(lm, r);
        }
    }

    // prologue arrives (complete phase 0: "step -1 spikes ready" = initial zeros)
    if (tid == 0) {
#pragma unroll
        for (int r = 0; r < CSIZE; r++)
            asm volatile("mbarrier.arrive.release.cluster.shared::cluster.b64 _, [%0];"
                         :: "r"(rmbar[r]) : "memory");
    }

    float v = -65.0f, adapt = 0.0f, thr = -55.0f, rsum = 0.0f;
    int   refr = 0;

    float* __restrict__ spikes_out = out;
    float* __restrict__ pot_out    = out + (size_t)T_STEPS * BATCH * NN;
    const size_t stride = (size_t)BATCH * NN;

    size_t ob = (size_t)b * NN + m;
    float Ie_next   = __ldg(Iext + ob);   // prefetch step 0
    float hist_next = 0.0f;

    int cur = 0;
    for (int t = 0; t < T_STEPS; t++) {
        const float Ie   = Ie_next;
        const float hist = hist_next;

        // ---- wait for all 8 CTAs' spike words of step t-1 (phase parity t&1)
        {
            const uint32_t mb = smem_u32(&mbar);
            const uint32_t parity = (uint32_t)(t & 1);
            uint32_t done;
            asm volatile("{\n\t.reg .pred p;\n\t"
                         "mbarrier.try_wait.parity.acquire.cluster.shared::cta.b64 p, [%1], %2;\n\t"
                         "selp.b32 %0, 1, 0, p;\n\t}"
                         : "=r"(done) : "r"(mb), "r"(parity) : "memory");
            while (!done) {
                asm volatile("{\n\t.reg .pred p;\n\t"
                             "mbarrier.try_wait.parity.acquire.cluster.shared::cta.b64 p, [%1], %2, 0x989680;\n\t"
                             "selp.b32 %0, 1, 0, p;\n\t}"
                             : "=r"(done) : "r"(mb), "r"(parity) : "memory");
            }
        }

        // ---- warp 0: scan bitmap[cur] -> dense spike list (deterministic order)
        if (wid == 0) {
            uint32_t w = bitmap[cur][lane];
            int c = __popc(w);
            int off = c;
#pragma unroll
            for (int d = 1; d < 32; d <<= 1) {
                int nb = __shfl_up_sync(0xffffffffu, off, d);
                if (lane >= d) off += nb;
            }
            off -= c;                          // exclusive prefix
            if (lane == 31) s_tot = off + c;
            int base = lane << 5;
            while (w) {
                int p = __ffs(w) - 1;
                combined[off++] = base + p;
                w &= w - 1;
            }
        }
        __syncthreads();

        // ---- sparse recurrent gather: I += sum_j W[j, m] over spiking j
        const int tot = s_tot;
        float acc = 0.0f;
        const float* __restrict__ Wm = W + m;
        int s = 0;
        for (; s + 4 <= tot; s += 4) {
            int j0 = combined[s], j1 = combined[s + 1];
            int j2 = combined[s + 2], j3 = combined[s + 3];
            float w0 = Wm[(size_t)j0 << 10];
            float w1 = Wm[(size_t)j1 << 10];
            float w2 = Wm[(size_t)j2 << 10];
            float w3 = Wm[(size_t)j3 << 10];
            acc += (w0 + w1) + (w2 + w3);
        }
        for (; s < tot; s++) acc += Wm[(size_t)combined[s] << 10];

        const float I = Ie + acc;

        // ---- neuron update (integrate -> fire/reset -> adapt -> homeo)
        const bool  active = (refr <= 0);
        const float v_int  = 0.9f * (v + 65.0f) - 65.0f + I - adapt;
        const float v1     = active ? v_int : v;
        const int   r1     = active ? refr : (refr - 1);
        const bool  fired  = (v1 >= thr);
        const float sp     = fired ? 1.0f : 0.0f;
        v     = fired ? -70.0f : v1;
        adapt = (fired ? (adapt + 0.2f) : adapt) * 0.95f;
        refr  = fired ? 5 : r1;

        // ---- push this warp's spike word to all peers' bitmap[nxt]
        const int nxt = cur ^ 1;
        const uint32_t word = __ballot_sync(0xffffffffu, fired);
        if (lane == 0) {
#pragma unroll
            for (int r = 0; r < CSIZE; r++)
                asm volatile("st.shared::cluster.u32 [%0], %1;"
                             :: "r"(rword[nxt][r]), "r"(word) : "memory");
        }
        __syncthreads();   // all warps' pushes ordered before the release arrive
        if (tid == 0) {
#pragma unroll
            for (int r = 0; r < CSIZE; r++)
                asm volatile("mbarrier.arrive.release.cluster.shared::cluster.b64 _, [%0];"
                             :: "r"(rmbar[r]) : "memory");
        }

        // ---- post-signal work (overlaps peers' progress)
        spikes_out[ob] = sp;
        pot_out[ob]    = v;
        rsum += sp - hist;
        if (t + 1 >= WHIST) {
            float ta = thr + 0.001f * (rsum * (1.0f / WHIST) - 0.01f);
            thr = fminf(fmaxf(ta, 0.1f), 5.0f);
        }

        const size_t ob_next = ob + stride;
        if (t + 1 < T_STEPS) {
            Ie_next   = __ldg(Iext + ob_next);
            hist_next = (t + 1 >= WHIST)
                      ? spikes_out[ob_next - (size_t)WHIST * stride] : 0.0f;
        }
        ob  = ob_next;
        cur = nxt;
    }

    // no CTA may exit while peers could still touch its smem
    asm volatile("barrier.cluster.arrive.aligned;" ::: "memory");
    asm volatile("barrier.cluster.wait.aligned;"   ::: "memory");
}

extern "C" void kernel_launch(void* const* d_in, const int* in_sizes, int n_in,
                              void* d_out, int out_size)
{
    const float* input_current = (const float*)d_in[0];  // [T,B,N]
    const float* W_rec         = (const float*)d_in[1];  // [N,N]
    float* out                 = (float*)d_out;          // [2,T,B,N]
    (void)in_sizes; (void)n_in; (void)out_size;

    mazebrain_kernel<<<BATCH * CSIZE, TPB>>>(input_current, W_rec, out);
}

// round 3
// speedup vs baseline: 2.4822x; 2.4822x over previous
#include <cuda_runtime.h>
#include <cstdint>

// MazeBrain: recurrent adaptive-LIF, T=1200, B=16, N=1024.
// One CTA per batch (no cross-SM sync). Spike exchange via shfl-built bitmap,
// warp-0 scan to dense list, 8-deep software-pipelined sparse gather.

#define T_STEPS 1200
#define BATCH   16
#define NN      1024
#define WHIST   1000
#define TPB     256     // thread owns neurons 4*tid .. 4*tid+3

__global__ void __launch_bounds__(TPB, 1)
mazebrain_kernel(const float* __restrict__ Iext,   // [T,B,N]
                 const float* __restrict__ W,      // [N,N]
                 float* __restrict__ out)          // [2,T,B,N]: spikes, potentials
{
    const int b    = blockIdx.x;
    const int tid  = threadIdx.x;
    const int m0   = tid * 4;
    const int lane = tid & 31;
    const int wid  = tid >> 5;

    __shared__ uint32_t words[2][32];   // 1024-bit spike bitmap, double-buffered
    __shared__ int      s_list[NN];     // dense spike list (single-buffered: see barriers)
    __shared__ int      s_tot;

    if (tid < 32) words[0][tid] = 0;    // step -1 spikes = 0; words[1] overwritten in step 0
    __syncthreads();

    float v[4], adapt[4], thr[4], rsum[4];
    int   refr[4];
#pragma unroll
    for (int k = 0; k < 4; k++) {
        v[k] = -65.0f; adapt[k] = 0.0f; thr[k] = -55.0f; rsum[k] = 0.0f; refr[k] = 0;
    }

    float* __restrict__ spikes_out = out;
    float* __restrict__ pot_out    = out + (size_t)T_STEPS * BATCH * NN;
    const size_t stride = (size_t)BATCH * NN;
    const float* __restrict__ Wm = W + m0;     // this thread's 4 columns

    size_t ob = (size_t)b * NN + m0;
    float4 Ie_next   = __ldg((const float4*)(Iext + ob));   // prefetch step 0
    float4 hist_next = make_float4(0.f, 0.f, 0.f, 0.f);

    int cur = 0;
    for (int t = 0; t < T_STEPS; t++) {
        const float4 Ie   = Ie_next;
        const float4 hist = hist_next;

        // ---- warp 0: scan words[cur] -> dense spike list (deterministic order)
        if (wid == 0) {
            uint32_t w = words[cur][lane];
            int c = __popc(w);
            int off = c;
#pragma unroll
            for (int d = 1; d < 32; d <<= 1) {
                int nb = __shfl_up_sync(0xffffffffu, off, d);
                if (lane >= d) off += nb;
            }
            if (lane == 31) s_tot = off;
            off -= c;                       // exclusive prefix
            int base = lane << 5;
            while (w) {
                int p = __ffs(w) - 1;
                s_list[off++] = base + p;
                w &= w - 1;
            }
        }
        __syncthreads();                    // list + s_tot visible to all

        // ---- sparse gather, 8-deep pipelined (high MLP on the L2 round-trips)
        const int tot = s_tot;
        float a0 = Ie.x, a1 = Ie.y, a2 = Ie.z, a3 = Ie.w;
        int s = 0;
        if (tot >= 8) {
            float4 r[8];
#pragma unroll
            for (int k = 0; k < 8; k++)
                r[k] = *(const float4*)(Wm + ((size_t)s_list[k] << 10));
            s = 8;
            while (s + 8 <= tot) {
                float4 rn[8];
#pragma unroll
                for (int k = 0; k < 8; k++)
                    rn[k] = *(const float4*)(Wm + ((size_t)s_list[s + k] << 10));
#pragma unroll
                for (int k = 0; k < 8; k++) {
                    a0 += r[k].x; a1 += r[k].y; a2 += r[k].z; a3 += r[k].w;
                }
#pragma unroll
                for (int k = 0; k < 8; k++) r[k] = rn[k];
                s += 8;
            }
#pragma unroll
            for (int k = 0; k < 8; k++) {
                a0 += r[k].x; a1 += r[k].y; a2 += r[k].z; a3 += r[k].w;
            }
        }
        for (; s < tot; s++) {
            float4 w4 = *(const float4*)(Wm + ((size_t)s_list[s] << 10));
            a0 += w4.x; a1 += w4.y; a2 += w4.z; a3 += w4.w;
        }
        float Iin[4] = {a0, a1, a2, a3};

        // ---- neuron update (integrate -> fire/reset -> adapt -> homeo)
        float spk[4], vout[4];
        uint32_t nib = 0;
#pragma unroll
        for (int k = 0; k < 4; k++) {
            bool  active = (refr[k] <= 0);
            float v_int  = 0.9f * (v[k] + 65.0f) - 65.0f + Iin[k] - adapt[k];
            float v1     = active ? v_int : v[k];
            int   r1     = active ? refr[k] : (refr[k] - 1);
            bool  fired  = (v1 >= thr[k]);
            spk[k]  = fired ? 1.0f : 0.0f;
            v[k]    = fired ? -70.0f : v1;
            vout[k] = v[k];
            adapt[k] = (fired ? (adapt[k] + 0.2f) : adapt[k]) * 0.95f;
            refr[k]  = fired ? 5 : r1;
            if (fired) nib |= (1u << k);
        }

        // ---- build next bitmap word via shfl-OR over groups of 8 threads
        const int nxt = cur ^ 1;
        nib <<= (tid & 7) * 4;
        nib |= __shfl_xor_sync(0xffffffffu, nib, 1);
        nib |= __shfl_xor_sync(0xffffffffu, nib, 2);
        nib |= __shfl_xor_sync(0xffffffffu, nib, 4);
        if ((tid & 7) == 0) words[nxt][tid >> 3] = nib;

        // ---- outputs (spikes array doubles as the 1000-step history ring)
        *(float4*)(spikes_out + ob) = make_float4(spk[0], spk[1], spk[2], spk[3]);
        *(float4*)(pot_out    + ob) = make_float4(vout[0], vout[1], vout[2], vout[3]);

        // ---- homeostatic sliding-window rate
        rsum[0] += spk[0] - hist.x; rsum[1] += spk[1] - hist.y;
        rsum[2] += spk[2] - hist.z; rsum[3] += spk[3] - hist.w;
        if (t + 1 >= WHIST) {
#pragma unroll
            for (int k = 0; k < 4; k++) {
                float ta = thr[k] + 0.001f * (rsum[k] * (1.0f / WHIST) - 0.01f);
                thr[k] = fminf(fmaxf(ta, 0.1f), 5.0f);
            }
        }

        // ---- prefetch next step's external current + history row
        const size_t ob_next = ob + stride;
        if (t + 1 < T_STEPS) {
            Ie_next = __ldg((const float4*)(Iext + ob_next));
            hist_next = (t + 1 >= WHIST)
                      ? *(const float4*)(spikes_out + (ob_next - (size_t)WHIST * stride))
                      : make_float4(0.f, 0.f, 0.f, 0.f);
        }
        ob  = ob_next;
        cur = nxt;

        __syncthreads();   // words[nxt] complete; list reads of this step done
    }
}

extern "C" void kernel_launch(void* const* d_in, const int* in_sizes, int n_in,
                              void* d_out, int out_size)
{
    const float* input_current = (const float*)d_in[0];  // [T,B,N]
    const float* W_rec         = (const float*)d_in[1];  // [N,N]
    float* out                 = (float*)d_out;          // [2,T,B,N]
    (void)in_sizes; (void)n_in; (void)out_size;

    mazebrain_kernel<<<BATCH, TPB>>>(input_current, W_rec, out);
}